// round 1
// baseline (speedup 1.0000x reference)
#include <cuda_runtime.h>

#define BATCH 64
#define UNUM  1024
#define ENUM  1024
#define UFD   512
#define EFD   256

// Scratch (allocation-free rule: __device__ globals)
__device__ float g_scale;
__device__ int   g_ne[BATCH];
__device__ float g_proj[(size_t)BATCH * UNUM * EFD];   // 64 MiB

// ---------------------------------------------------------------------------
// K0: scale = g / ||v||_F  +  robust num_enemy decode (int32 vs int64 layout)
// ---------------------------------------------------------------------------
__global__ __launch_bounds__(1024) void prep_kernel(const float* __restrict__ v,
                                                    const float* __restrict__ g,
                                                    const int* __restrict__ ne32) {
    __shared__ float wsum[32];
    int tid = threadIdx.x;
    float s = 0.f;
    for (int i = tid; i < EFD * UFD; i += 1024) { float x = v[i]; s += x * x; }
    #pragma unroll
    for (int o = 16; o; o >>= 1) s += __shfl_xor_sync(0xffffffffu, s, o);
    if ((tid & 31) == 0) wsum[tid >> 5] = s;
    __syncthreads();
    if (tid == 0) {
        float tot = 0.f;
        #pragma unroll
        for (int w = 0; w < 32; w++) tot += wsum[w];
        g_scale = g[0] / sqrtf(tot);

        // Detect int64 vs int32 num_enemy: int64 little-endian values < 1024
        // have zero high words. 32 random int32 values all being zero is
        // probabilistically impossible. Only reads within 256B until decided.
        bool is64 = true;
        for (int i = 0; i < 32; i++) {
            if (ne32[2 * i + 1] != 0) { is64 = false; break; }
        }
        for (int i = 0; i < BATCH; i++) g_ne[i] = is64 ? ne32[2 * i] : ne32[i];
    }
}

// ---------------------------------------------------------------------------
// Tiled fp32 GEMM  C = A (MxK, row-major) * B^T (B is NxK row-major)
// BM=BN=128, BK=16, 256 threads, 8x8 microtile.
// MODE 0: proj  = relu(g_scale*acc + bias[n])            -> g_proj
// MODE 1: logit = acc/16 - (n >= num_enemy[z] ? 1e9 : 0) -> d_out (per batch z)
// ---------------------------------------------------------------------------
template<int K, int MODE>
__global__ __launch_bounds__(256) void gemm_tn(const float* __restrict__ A,
                                               const float* __restrict__ B,
                                               float* __restrict__ C,
                                               const float* __restrict__ bias) {
    __shared__ float As[16][129];
    __shared__ float Bs[16][129];

    if (MODE == 1) {
        size_t z = blockIdx.z;
        A = g_proj + z * (size_t)(UNUM * EFD);
        B += z * (size_t)(ENUM * EFD);
        C += z * (size_t)(UNUM * ENUM);
    }
    float* Cw = (MODE == 0) ? g_proj : C;

    const int m0 = blockIdx.y * 128;
    const int n0 = blockIdx.x * 128;
    const int t  = threadIdx.x;
    const int ty = t >> 4;     // m-direction (16)
    const int tx = t & 15;     // n-direction (16)

    float acc[8][8] = {};

    #pragma unroll 1
    for (int k0 = 0; k0 < K; k0 += 16) {
        __syncthreads();
        #pragma unroll
        for (int i = 0; i < 2; i++) {
            int f  = t + i * 256;        // float4 index, 512 total per tile
            int r  = f >> 2;             // row within tile (0..127)
            int kq = (f & 3) << 2;       // k offset (0,4,8,12)
            float4 a = *(const float4*)(A + (size_t)(m0 + r) * K + k0 + kq);
            As[kq + 0][r] = a.x; As[kq + 1][r] = a.y;
            As[kq + 2][r] = a.z; As[kq + 3][r] = a.w;
            float4 bb = *(const float4*)(B + (size_t)(n0 + r) * K + k0 + kq);
            Bs[kq + 0][r] = bb.x; Bs[kq + 1][r] = bb.y;
            Bs[kq + 2][r] = bb.z; Bs[kq + 3][r] = bb.w;
        }
        __syncthreads();

        #pragma unroll
        for (int k = 0; k < 16; k++) {
            float ar[8], br[8];
            #pragma unroll
            for (int i = 0; i < 8; i++) ar[i] = As[k][ty * 8 + i];
            #pragma unroll
            for (int j = 0; j < 8; j++) br[j] = Bs[k][tx * 8 + j];
            #pragma unroll
            for (int i = 0; i < 8; i++)
                #pragma unroll
                for (int j = 0; j < 8; j++)
                    acc[i][j] = fmaf(ar[i], br[j], acc[i][j]);
        }
    }

    if (MODE == 0) {
        float s = g_scale;
        #pragma unroll
        for (int i = 0; i < 8; i++) {
            int m = m0 + ty * 8 + i;
            float* crow = Cw + (size_t)m * EFD + n0 + tx * 8;
            #pragma unroll
            for (int j = 0; j < 8; j++) {
                float p = fmaf(s, acc[i][j], bias[n0 + tx * 8 + j]);
                crow[j] = fmaxf(p, 0.f);
            }
        }
    } else {
        int ne = g_ne[blockIdx.z];
        #pragma unroll
        for (int i = 0; i < 8; i++) {
            int m = m0 + ty * 8 + i;
            float* crow = Cw + (size_t)m * ENUM + n0 + tx * 8;
            #pragma unroll
            for (int j = 0; j < 8; j++) {
                int n = n0 + tx * 8 + j;
                float l = acc[i][j] * 0.0625f;       // /sqrt(256)
                if (n >= ne) l -= 1e9f;              // fp32 rounds to exactly -1e9
                crow[j] = l;
            }
        }
    }
}

// ---------------------------------------------------------------------------
// In-place row softmax over d_out: 65536 rows x 1024. One warp per row,
// whole row cached in registers (8 x float4 per lane).
// ---------------------------------------------------------------------------
__global__ __launch_bounds__(256) void softmax_kernel(float* __restrict__ out) {
    int lane   = threadIdx.x & 31;
    size_t row = (size_t)blockIdx.x * 8 + (threadIdx.x >> 5);
    float4* p  = reinterpret_cast<float4*>(out) + row * 256;

    float4 x[8];
    float m = -3.402823466e38f;
    #pragma unroll
    for (int j = 0; j < 8; j++) {
        x[j] = p[lane + 32 * j];
        m = fmaxf(m, fmaxf(fmaxf(x[j].x, x[j].y), fmaxf(x[j].z, x[j].w)));
    }
    #pragma unroll
    for (int o = 16; o; o >>= 1) m = fmaxf(m, __shfl_xor_sync(0xffffffffu, m, o));

    float s = 0.f;
    #pragma unroll
    for (int j = 0; j < 8; j++) {
        x[j].x = __expf(x[j].x - m);
        x[j].y = __expf(x[j].y - m);
        x[j].z = __expf(x[j].z - m);
        x[j].w = __expf(x[j].w - m);
        s += (x[j].x + x[j].y) + (x[j].z + x[j].w);
    }
    #pragma unroll
    for (int o = 16; o; o >>= 1) s += __shfl_xor_sync(0xffffffffu, s, o);

    float inv = 1.f / s;
    #pragma unroll
    for (int j = 0; j < 8; j++) {
        x[j].x *= inv; x[j].y *= inv; x[j].z *= inv; x[j].w *= inv;
        p[lane + 32 * j] = x[j];
    }
}

// ---------------------------------------------------------------------------
extern "C" void kernel_launch(void* const* d_in, const int* in_sizes, int n_in,
                              void* d_out, int out_size) {
    const float* ufeat = (const float*)d_in[0];   // [64,1024,512]
    const float* efeat = (const float*)d_in[1];   // [64,1024,256]
    const int*   neptr = (const int*)d_in[2];     // [64] int32 or int64
    const float* v     = (const float*)d_in[3];   // [256,512]
    const float* g     = (const float*)d_in[4];   // scalar
    const float* bias  = (const float*)d_in[5];   // [256]
    float* out = (float*)d_out;                   // [64,1024,1024]

    prep_kernel<<<1, 1024>>>(v, g, neptr);

    // proj: M=65536, N=256, K=512
    gemm_tn<UFD, 0><<<dim3(EFD / 128, (BATCH * UNUM) / 128, 1), 256>>>(
        ufeat, v, nullptr, bias);

    // logits+mask: per batch, M=1024, N=1024, K=256
    gemm_tn<EFD, 1><<<dim3(ENUM / 128, UNUM / 128, BATCH), 256>>>(
        nullptr, efeat, out, nullptr);

    // softmax in-place
    softmax_kernel<<<(BATCH * UNUM) / 8, 256>>>(out);
}

// round 4
// speedup vs baseline: 2.4889x; 2.4889x over previous
#include <cuda_runtime.h>
#include <cstdint>

#define BATCH 64
#define UNUM  1024
#define ENUM  1024
#define UFD   512
#define EFD   256

__device__ float g_scale;
__device__ int   g_ne[BATCH];
__device__ float g_proj[(size_t)BATCH * UNUM * EFD];   // 64 MiB scratch

// ---------------------------------------------------------------------------
// K0: scale = g / ||v||_F  +  robust num_enemy decode (int32 vs int64 layout)
// ---------------------------------------------------------------------------
__global__ __launch_bounds__(1024) void prep_kernel(const float* __restrict__ v,
                                                    const float* __restrict__ g,
                                                    const int* __restrict__ ne32) {
    __shared__ float wsum[32];
    int tid = threadIdx.x;
    float s = 0.f;
    for (int i = tid; i < EFD * UFD; i += 1024) { float x = v[i]; s += x * x; }
    #pragma unroll
    for (int o = 16; o; o >>= 1) s += __shfl_xor_sync(0xffffffffu, s, o);
    if ((tid & 31) == 0) wsum[tid >> 5] = s;
    __syncthreads();
    if (tid == 0) {
        float tot = 0.f;
        #pragma unroll
        for (int w = 0; w < 32; w++) tot += wsum[w];
        g_scale = g[0] / sqrtf(tot);
        bool is64 = true;
        for (int i = 0; i < 32; i++)
            if (ne32[2 * i + 1] != 0) { is64 = false; break; }
        for (int i = 0; i < BATCH; i++) g_ne[i] = is64 ? ne32[2 * i] : ne32[i];
    }
}

// ---------------------------------------------------------------------------
// bf16x2 split-precision mma.sync GEMM:  C = A(MxK) * B(NxK)^T (fp32 in/out).
// Each fp32 x -> hi=bf16(x), lo=bf16(x-hi); A*B = Ahi*Bhi + Ahi*Blo + Alo*Bhi.
// Tile 128x128, BK=32, 256 threads (8 warps: 2m x 4n), warp tile 64x32.
// SMEM per buffer (words): A_hi[2048] A_lo[2048] B_hi[2048] B_lo[2048],
// all pre-permuted into m16n8k16 fragment order:
//   A: [kstep(2)][m16(8)][lane(32)][reg(4)] -> one LDS.128 per fragment
//   B: [kstep(2)][n8(16)][lane(32)][reg(2)] -> one LDS.64  per fragment
// MODE 0: proj  = relu(g_scale*acc + bias[n])            -> g_proj
// MODE 1: logit = acc/16 - (n >= num_enemy[z] ? 1e9 : 0) -> d_out
// ---------------------------------------------------------------------------
#define SMEM_BYTES (2 * 8192 * 4)   // 64 KB

__device__ __forceinline__ uint32_t packbf(float x0, float x1) {
    // result = {hi16: bf16(x1), lo16: bf16(x0)}  (x0 = even k)
    uint32_t r;
    asm("cvt.rn.bf16x2.f32 %0, %1, %2;" : "=r"(r) : "f"(x1), "f"(x0));
    return r;
}
__device__ __forceinline__ uint32_t lopack(uint32_t h, float x0, float x1) {
    float l0 = x0 - __uint_as_float(h << 16);
    float l1 = x1 - __uint_as_float(h & 0xffff0000u);
    return packbf(l0, l1);
}

__device__ __forceinline__ void mma_bf16(float* d, const uint32_t* a, const uint32_t* b) {
    asm volatile(
        "mma.sync.aligned.m16n8k16.row.col.f32.bf16.bf16.f32 "
        "{%0,%1,%2,%3}, {%4,%5,%6,%7}, {%8,%9}, {%0,%1,%2,%3};"
        : "+f"(d[0]), "+f"(d[1]), "+f"(d[2]), "+f"(d[3])
        : "r"(a[0]), "r"(a[1]), "r"(a[2]), "r"(a[3]), "r"(b[0]), "r"(b[1]));
}

template<int K, int MODE>
__global__ __launch_bounds__(256) void gemm_mma(const float* __restrict__ Ag,
                                                const float* __restrict__ Bg,
                                                float* __restrict__ C,
                                                const float* __restrict__ bias) {
    extern __shared__ uint32_t smem[];

    const int t = threadIdx.x;
    const int warp = t >> 5, lane = t & 31;
    const int warpM = warp >> 2;         // 0..1 -> 64 rows
    const int warpN = warp & 3;          // 0..3 -> 32 cols

    int m0, n0, ne = 0;
    const float *Aq, *Bq;
    float* Cw;
    int ldc;
    if (MODE == 0) {
        m0 = blockIdx.y * 128; n0 = blockIdx.x * 128;
        Aq = Ag; Bq = Bg; Cw = g_proj; ldc = EFD;
    } else {
        int z = blockIdx.z;
        m0 = blockIdx.y * 128; n0 = blockIdx.x * 128;
        Aq = g_proj + (size_t)z * UNUM * EFD;
        Bq = Bg + (size_t)z * ENUM * EFD;
        Cw = C + (size_t)z * UNUM * ENUM;
        ldc = ENUM;
        ne = g_ne[z];
    }

    float acc[4][4][4];
    #pragma unroll
    for (int i = 0; i < 4; i++)
        #pragma unroll
        for (int j = 0; j < 4; j++)
            #pragma unroll
            for (int r = 0; r < 4; r++) acc[i][j][r] = 0.f;

    float4 va[4], vb[4];
    constexpr int NB = K / 32;

    auto load_tile = [&](int kb) {
        const int k0 = kb * 32;
        #pragma unroll
        for (int i = 0; i < 4; i++) {
            int f = t + i * 256, row = f >> 3, q = f & 7;
            va[i] = *(const float4*)(Aq + (size_t)(m0 + row) * K + k0 + q * 4);
            vb[i] = *(const float4*)(Bq + (size_t)(n0 + row) * K + k0 + q * 4);
        }
    };

    auto store_tile = [&](int buf) {
        uint32_t* base = smem + buf * 8192;
        #pragma unroll
        for (int i = 0; i < 4; i++) {
            int f = t + i * 256, row = f >> 3, q = f & 7;
            const int kstep = q >> 2;
            const int hp = ((q & 3) * 2) & 3;        // fragment k-pair lane slot
            const int kr = (q & 3) >> 1;             // k>=8 half -> +2 on A reg / +1 on B reg
            // ---- A ----
            {
                int m16 = row >> 4, r16 = row & 15;
                int reg = (r16 >> 3) + 2 * kr;
                uint32_t* p = base + ((kstep * 8 + m16) * 32 + (r16 & 7) * 4 + hp) * 4 + reg;
                uint32_t h0 = packbf(va[i].x, va[i].y);
                uint32_t h1 = packbf(va[i].z, va[i].w);
                p[0] = h0;
                p[4] = h1;                           // lane+1
                p[2048 + 0] = lopack(h0, va[i].x, va[i].y);
                p[2048 + 4] = lopack(h1, va[i].z, va[i].w);
            }
            // ---- B ----
            {
                int n8 = row >> 3;
                uint32_t* p = base + 4096 +
                    ((kstep * 16 + n8) * 32 + (row & 7) * 4 + hp) * 2 + kr;
                uint32_t h0 = packbf(vb[i].x, vb[i].y);
                uint32_t h1 = packbf(vb[i].z, vb[i].w);
                p[0] = h0;
                p[2] = h1;                           // lane+1
                p[2048 + 0] = lopack(h0, vb[i].x, vb[i].y);
                p[2048 + 2] = lopack(h1, vb[i].z, vb[i].w);
            }
        }
    };

    auto compute = [&](int buf) {
        const uint32_t* sA = smem + buf * 8192;
        const uint32_t* sB = sA + 4096;
        #pragma unroll
        for (int ks = 0; ks < 2; ks++) {
            uint4 ah[4], al[4];
            uint2 bh[4], bl[4];
            #pragma unroll
            for (int mt = 0; mt < 4; mt++) {
                int idx = (ks * 8 + warpM * 4 + mt) * 32 + lane;
                ah[mt] = ((const uint4*)sA)[idx];
                al[mt] = ((const uint4*)(sA + 2048))[idx];
            }
            #pragma unroll
            for (int nt = 0; nt < 4; nt++) {
                int jdx = (ks * 16 + warpN * 4 + nt) * 32 + lane;
                bh[nt] = ((const uint2*)sB)[jdx];
                bl[nt] = ((const uint2*)(sB + 2048))[jdx];
            }
            #pragma unroll
            for (int mt = 0; mt < 4; mt++)
                #pragma unroll
                for (int nt = 0; nt < 4; nt++) {
                    mma_bf16(acc[mt][nt], (const uint32_t*)&ah[mt], (const uint32_t*)&bh[nt]);
                    mma_bf16(acc[mt][nt], (const uint32_t*)&ah[mt], (const uint32_t*)&bl[nt]);
                    mma_bf16(acc[mt][nt], (const uint32_t*)&al[mt], (const uint32_t*)&bh[nt]);
                }
        }
    };

    load_tile(0);
    store_tile(0);
    #pragma unroll 1
    for (int kb = 0; kb < NB; kb++) {
        __syncthreads();
        if (kb + 1 < NB) load_tile(kb + 1);
        compute(kb & 1);
        if (kb + 1 < NB) store_tile((kb + 1) & 1);
    }

    // ---- epilogue: c0,c1 -> (rowL, col, col+1); c2,c3 -> rowL+8 ----
    const int rbase = m0 + warpM * 64 + (lane >> 2);
    const int cbase = n0 + warpN * 32 + (lane & 3) * 2;
    if (MODE == 0) {
        const float s = g_scale;
        #pragma unroll
        for (int mt = 0; mt < 4; mt++) {
            int rL = rbase + mt * 16;
            #pragma unroll
            for (int nt = 0; nt < 4; nt++) {
                int cb = cbase + nt * 8;
                float b0 = bias[cb], b1 = bias[cb + 1];   // global column index
                float2 o0, o1;
                o0.x = fmaxf(fmaf(s, acc[mt][nt][0], b0), 0.f);
                o0.y = fmaxf(fmaf(s, acc[mt][nt][1], b1), 0.f);
                o1.x = fmaxf(fmaf(s, acc[mt][nt][2], b0), 0.f);
                o1.y = fmaxf(fmaf(s, acc[mt][nt][3], b1), 0.f);
                *(float2*)(Cw + (size_t)rL * ldc + cb) = o0;
                *(float2*)(Cw + (size_t)(rL + 8) * ldc + cb) = o1;
            }
        }
    } else {
        #pragma unroll
        for (int mt = 0; mt < 4; mt++) {
            int rL = rbase + mt * 16;
            #pragma unroll
            for (int nt = 0; nt < 4; nt++) {
                int cb = cbase + nt * 8;
                float m0f = (cb + 0 >= ne) ? 1e9f : 0.f;
                float m1f = (cb + 1 >= ne) ? 1e9f : 0.f;
                float2 o0, o1;
                o0.x = acc[mt][nt][0] * 0.0625f - m0f;
                o0.y = acc[mt][nt][1] * 0.0625f - m1f;
                o1.x = acc[mt][nt][2] * 0.0625f - m0f;
                o1.y = acc[mt][nt][3] * 0.0625f - m1f;
                *(float2*)(Cw + (size_t)rL * ldc + cb) = o0;
                *(float2*)(Cw + (size_t)(rL + 8) * ldc + cb) = o1;
            }
        }
    }
}

// ---------------------------------------------------------------------------
// In-place row softmax: 65536 rows x 1024, one warp per row, row in registers.
// ---------------------------------------------------------------------------
__global__ __launch_bounds__(256) void softmax_kernel(float* __restrict__ out) {
    int lane   = threadIdx.x & 31;
    size_t row = (size_t)blockIdx.x * 8 + (threadIdx.x >> 5);
    float4* p  = reinterpret_cast<float4*>(out) + row * 256;

    float4 x[8];
    float m = -3.402823466e38f;
    #pragma unroll
    for (int j = 0; j < 8; j++) {
        x[j] = p[lane + 32 * j];
        m = fmaxf(m, fmaxf(fmaxf(x[j].x, x[j].y), fmaxf(x[j].z, x[j].w)));
    }
    #pragma unroll
    for (int o = 16; o; o >>= 1) m = fmaxf(m, __shfl_xor_sync(0xffffffffu, m, o));

    float s = 0.f;
    #pragma unroll
    for (int j = 0; j < 8; j++) {
        x[j].x = __expf(x[j].x - m);
        x[j].y = __expf(x[j].y - m);
        x[j].z = __expf(x[j].z - m);
        x[j].w = __expf(x[j].w - m);
        s += (x[j].x + x[j].y) + (x[j].z + x[j].w);
    }
    #pragma unroll
    for (int o = 16; o; o >>= 1) s += __shfl_xor_sync(0xffffffffu, s, o);

    float inv = 1.f / s;
    #pragma unroll
    for (int j = 0; j < 8; j++) {
        x[j].x *= inv; x[j].y *= inv; x[j].z *= inv; x[j].w *= inv;
        p[lane + 32 * j] = x[j];
    }
}

// ---------------------------------------------------------------------------
extern "C" void kernel_launch(void* const* d_in, const int* in_sizes, int n_in,
                              void* d_out, int out_size) {
    const float* ufeat = (const float*)d_in[0];   // [64,1024,512]
    const float* efeat = (const float*)d_in[1];   // [64,1024,256]
    const int*   neptr = (const int*)d_in[2];     // [64] int32 or int64
    const float* v     = (const float*)d_in[3];   // [256,512]
    const float* g     = (const float*)d_in[4];   // scalar
    const float* bias  = (const float*)d_in[5];   // [256]
    float* out = (float*)d_out;                   // [64,1024,1024]

    cudaFuncSetAttribute(gemm_mma<UFD, 0>, cudaFuncAttributeMaxDynamicSharedMemorySize, SMEM_BYTES);
    cudaFuncSetAttribute(gemm_mma<EFD, 1>, cudaFuncAttributeMaxDynamicSharedMemorySize, SMEM_BYTES);

    prep_kernel<<<1, 1024>>>(v, g, neptr);

    // proj: M=65536, N=256, K=512
    gemm_mma<UFD, 0><<<dim3(EFD / 128, (BATCH * UNUM) / 128, 1), 256, SMEM_BYTES>>>(
        ufeat, v, nullptr, bias);

    // logits+mask: per batch, M=1024, N=1024, K=256
    gemm_mma<EFD, 1><<<dim3(ENUM / 128, UNUM / 128, BATCH), 256, SMEM_BYTES>>>(
        nullptr, efeat, out, nullptr);

    softmax_kernel<<<(BATCH * UNUM) / 8, 256>>>(out);
}